// round 16
// baseline (speedup 1.0000x reference)
#include <cuda_runtime.h>
#include <cstdint>

#define DIM 128
#define NSLICE 16          // k-slices per batch
#define NTHREADS 256       // 8 warps per block
#define NBATCH 8

typedef unsigned long long u64t;

// ---------------- tagged dataflow scratch (static __device__, zero-init) ----------
// word = (tag<<32) | float_bits; single 8B store publishes value+readiness together.
__device__ u64t g_h2x[NBATCH][5 * DIM];   // rows 2j||2j+1 contiguous
__device__ u64t g_tbx[NBATCH][2 * DIM];
__device__ u64t g_h1x[NBATCH][2 * DIM];   // rows 0||1 contiguous
__device__ u64t g_tb0x[NBATCH][DIM];
__device__ u64t g_epoch;                  // +1 per block per launch (128/launch)

__device__ __forceinline__ float prelu_f(float x, float a) {
    return x >= 0.0f ? x : a * x;
}

// xor-butterfly: full sum in EVERY lane
__device__ __forceinline__ float wred(float v) {
    v += __shfl_xor_sync(0xffffffffu, v, 16);
    v += __shfl_xor_sync(0xffffffffu, v, 8);
    v += __shfl_xor_sync(0xffffffffu, v, 4);
    v += __shfl_xor_sync(0xffffffffu, v, 2);
    v += __shfl_xor_sync(0xffffffffu, v, 1);
    return v;
}

__device__ __forceinline__ void st_tag(u64t* p, float val, unsigned tag) {
    u64t v = ((u64t)tag << 32) | (u64t)__float_as_uint(val);
    asm volatile("st.relaxed.gpu.global.u64 [%0], %1;" :: "l"(p), "l"(v) : "memory");
}

// ONE warp polls 32*N tagged words (lane l owns words l*N..l*N+N-1) until all
// tags match, then broadcasts the float values into smem dst.
template<int N>
__device__ __forceinline__ void poll_bcast(const u64t* __restrict__ src,
                                           float* __restrict__ dst,
                                           unsigned tag, int l) {
    u64t v[N];
    for (;;) {
        bool ok = true;
        #pragma unroll
        for (int i = 0; i < N; i++)
            asm volatile("ld.relaxed.gpu.global.u64 %0, [%1];"
                         : "=l"(v[i]) : "l"(src + l * N + i) : "memory");
        #pragma unroll
        for (int i = 0; i < N; i++)
            ok &= ((unsigned)(v[i] >> 32) == tag);
        if (__all_sync(0xffffffffu, ok)) break;
    }
    #pragma unroll
    for (int i = 0; i < N; i++)
        dst[l * N + i] = __uint_as_float((unsigned)(v[i] & 0xffffffffu));
}

// load 8 consecutive smem floats (32B-aligned) into x[8]
__device__ __forceinline__ void ld8s(const float* p, float* x) {
    float4 a = ((const float4*)p)[0];
    float4 b = ((const float4*)p)[1];
    x[0]=a.x; x[1]=a.y; x[2]=a.z; x[3]=a.w;
    x[4]=b.x; x[5]=b.y; x[6]=b.z; x[7]=b.w;
}

__global__ __launch_bounds__(NTHREADS, 1) void encoder_fused_kernel(
    const float* __restrict__ points,  // [B, N3, 3]
    const float* __restrict__ vec2,    // [B, N2, 3]
    const float* __restrict__ vec1,    // [B, N1, 3]
    const float* __restrict__ vec0,    // [B, 1, 3]
    const float* __restrict__ Wp,      // [DIM, 3]
    const float* __restrict__ bp,
    const float* __restrict__ a_leaf,
    const float* __restrict__ Wb2, const float* __restrict__ bb2,
    const float* __restrict__ a2p,
    const float* __restrict__ Wb1, const float* __restrict__ bb1,
    const float* __restrict__ Ws1, const float* __restrict__ bs1,
    const float* __restrict__ a1p,
    const float* __restrict__ Wb0, const float* __restrict__ bb0,
    const float* __restrict__ Ws0, const float* __restrict__ bs0,
    const float* __restrict__ a0p,
    const int* __restrict__ cl2, const int* __restrict__ cr2,
    const int* __restrict__ cl1, const int* __restrict__ cr1,
    const int* __restrict__ cs1,
    const int* __restrict__ cl0, const int* __restrict__ cr0,
    const int* __restrict__ cs0,
    float* __restrict__ out,           // [B, DIM]
    int N3, int N2n, int N1n)
{
    const int b   = blockIdx.x >> 4;
    const int s   = blockIdx.x & (NSLICE - 1);
    const int tid = threadIdx.x;
    const int w   = tid >> 5, l = tid & 31;

    // ---------------- work mapping ----------------
    const int kB  = (s << 3) + w;           // phase B/E/F channel
    const int idx = (s << 4) + (w << 1);    // phase C/D pair base
    const int jCD = idx >> 7;               // SAME for all warps of a block
    const int k0  = idx & 127, k1 = k0 + 1;

    // ---- preload ONLY Phase-B weights up front; rest deferred into poll windows ----
    float wBr[24];
    {
        const float4* pB = (const float4*)(Wb2 + (long)kB * 768 + 24 * l);
        #pragma unroll
        for (int i = 0; i < 6; i++) ((float4*)wBr)[i] = pB[i];
    }
    const float bB  = bb2[kB];
    const float bC0 = bb1[k0], bC1 = bb1[k1];
    const float bD0 = bs1[k0], bD1 = bs1[k1];
    const float bE  = bb0[kB], bF = bs0[kB];
    const float AL = a_leaf[0], A2 = a2p[0], A1 = a1p[0], A0 = a0p[0];

    __shared__ int sroot[3];
    __shared__ unsigned stag;
    __shared__ int scl1[1024], scr1[1024], scs1[1024];   // level-1 tables (12KB)
    __shared__ int sp[12];
    __shared__ __align__(16) float svec2[5][3];
    __shared__ __align__(16) float svec1[2][3];
    __shared__ __align__(16) float svec0[3];
    __shared__ __align__(16) float leaf[12][DIM];
    __shared__ __align__(16) float xc[2 * DIM];    // h2 rows 2jCD..2jCD+1
    __shared__ __align__(16) float xh24[DIM];      // h2 row 4 (for F)
    __shared__ __align__(16) float xd[DIM];        // tb row jCD
    __shared__ __align__(16) float xe[2 * DIM];    // h1 rows 0..1
    __shared__ __align__(16) float xf[DIM];        // tb0

    const bool bulk = (N1n == 1024);

    // ---- Round 1: epoch + root indices (thread 0) || level-1 table bulk load ----
    if (tid == 0) {
        u64t old = atomicAdd(&g_epoch, 1ull);
        stag = (unsigned)(old / (NBATCH * NSLICE)) + 1u;   // uniform across blocks
        sroot[0] = cl0[0]; sroot[1] = cr0[0]; sroot[2] = cs0[0];
    }
    if (bulk) {
        #pragma unroll
        for (int i = 0; i < 4; i++) {
            int j = tid + i * NTHREADS;
            scl1[j] = cl1[j];
            scr1[j] = cr1[j];
            scs1[j] = cs1[j];
        }
    }
    __syncthreads();
    const unsigned tag = stag;

    const int l1a = sroot[0], l1b = sroot[1], n4 = sroot[2];
    int n0, n1, n2_, n3;
    if (bulk) {
        n0 = scl1[l1a]; n1 = scr1[l1a]; n2_ = scl1[l1b]; n3 = scr1[l1b];
    } else {
        n0 = cl1[l1a];  n1 = cr1[l1a];  n2_ = cl1[l1b];  n3 = cr1[l1b];
    }

    // ---- Round 2: distributed cl2/cr2 gather + sample leaves + ALL vec gathers ----
    if (tid < 10) {
        int j = tid >> 1;
        int node = (j == 0) ? n0 : (j == 1) ? n1 : (j == 2) ? n2_ : (j == 3) ? n3 : n4;
        sp[tid] = (tid & 1) ? cr2[node] : cl2[node];
    } else if (tid == 10) {
        sp[10] = bulk ? scs1[l1a] : cs1[l1a];
    } else if (tid == 11) {
        sp[11] = bulk ? scs1[l1b] : cs1[l1b];
    } else if (tid >= 32 && tid < 47) {
        int t = tid - 32;
        int j = t / 3, v = t - 3 * j;
        int node = (j == 0) ? n0 : (j == 1) ? n1 : (j == 2) ? n2_ : (j == 3) ? n3 : n4;
        svec2[j][v] = vec2[((long)b * N2n + node) * 3 + v];
    } else if (tid >= 47 && tid < 53) {
        int t = tid - 47;
        int j = t / 3, v = t - 3 * j;
        svec1[j][v] = vec1[((long)b * N1n + (j == 0 ? l1a : l1b)) * 3 + v];
    } else if (tid >= 53 && tid < 56) {
        svec0[tid - 53] = vec0[(long)b * 3 + (tid - 53)];
    }
    __syncthreads();

    // ---- Round 3: leaves: 12 rows, h3 = prelu(points @ Wp^T + bp) ----
    for (int i = tid; i < 12 * DIM; i += NTHREADS) {
        int j = i >> 7, k = i & 127;
        const float* pt = points + ((long)b * N3 + sp[j]) * 3;
        float h = fmaf(Wp[k * 3 + 0], pt[0],
                  fmaf(Wp[k * 3 + 1], pt[1],
                  fmaf(Wp[k * 3 + 2], pt[2], bp[k])));
        leaf[j][k] = prelu_f(h, AL);
    }
    __syncthreads();

    // ---- Phase B: layer-2 bilinear, 5 nodes; publish tagged h2 ----
    {
        #pragma unroll
        for (int j = 0; j < 5; j++) {
            float x[8];
            ld8s(&leaf[2 * j][0] + 8 * l, x);
            float a0 = 0.f, a1 = 0.f, a2 = 0.f;
            #pragma unroll
            for (int m = 0; m < 8; m++) {
                a0 = fmaf(x[m], wBr[3 * m + 0], a0);
                a1 = fmaf(x[m], wBr[3 * m + 1], a1);
                a2 = fmaf(x[m], wBr[3 * m + 2], a2);
            }
            float z = a0 * svec2[j][0] + a1 * svec2[j][1] + a2 * svec2[j][2];
            float r = wred(z);
            if (l == 0)
                st_tag(&g_h2x[b][j * DIM + kB], prelu_f(r + bB, A2), tag);
        }
    }

    // ---- Boundary C: warp0 polls h2 rows 2jCD..+1; warp1 polls row 4;
    //      others load Phase-C weights during the wait ----
    float wC0r[24], wC1r[24];
    {
        const float4* pC0 = (const float4*)(Wb1 + (long)k0 * 768 + 24 * l);
        const float4* pC1 = (const float4*)(Wb1 + (long)k1 * 768 + 24 * l);
        #pragma unroll
        for (int i = 0; i < 6; i++) {
            ((float4*)wC0r)[i] = pC0[i];
            ((float4*)wC1r)[i] = pC1[i];
        }
    }
    if (w == 0) poll_bcast<8>(&g_h2x[b][2 * jCD * DIM], xc, tag, l);
    if (w == 1) poll_bcast<4>(&g_h2x[b][4 * DIM], xh24, tag, l);
    __syncthreads();

    // ---- Phase C: layer-1 bilinear from smem xc; publish tagged tb ----
    {
        float x[8];
        ld8s(&xc[8 * l], x);
        float a00 = 0.f, a01 = 0.f, a02 = 0.f;
        float a10 = 0.f, a11 = 0.f, a12 = 0.f;
        #pragma unroll
        for (int m = 0; m < 8; m++) {
            a00 = fmaf(x[m], wC0r[3 * m + 0], a00);
            a01 = fmaf(x[m], wC0r[3 * m + 1], a01);
            a02 = fmaf(x[m], wC0r[3 * m + 2], a02);
            a10 = fmaf(x[m], wC1r[3 * m + 0], a10);
            a11 = fmaf(x[m], wC1r[3 * m + 1], a11);
            a12 = fmaf(x[m], wC1r[3 * m + 2], a12);
        }
        float z0 = a00 * svec1[jCD][0] + a01 * svec1[jCD][1] + a02 * svec1[jCD][2];
        float z1 = a10 * svec1[jCD][0] + a11 * svec1[jCD][1] + a12 * svec1[jCD][2];
        float r0 = wred(z0), r1 = wred(z1);
        if (l == 0)      st_tag(&g_tbx[b][jCD * DIM + k0], prelu_f(r0 + bC0, A1), tag);
        else if (l == 1) st_tag(&g_tbx[b][jCD * DIM + k1], prelu_f(r1 + bC1, A1), tag);
    }

    // ---- Boundary D: warp0 polls tb row jCD; others load Phase-D/E weights ----
    float wD0r[8], wD1r[8], wEr[24];
    {
        const float4* pD0 = (const float4*)(Ws1 + (long)k0 * 256 + 8 * l);
        const float4* pD1 = (const float4*)(Ws1 + (long)k1 * 256 + 8 * l);
        const float4* pE  = (const float4*)(Wb0 + (long)kB * 768 + 24 * l);
        ((float4*)wD0r)[0] = pD0[0]; ((float4*)wD0r)[1] = pD0[1];
        ((float4*)wD1r)[0] = pD1[0]; ((float4*)wD1r)[1] = pD1[1];
        #pragma unroll
        for (int i = 0; i < 6; i++) ((float4*)wEr)[i] = pE[i];
    }
    if (w == 0) poll_bcast<4>(&g_tbx[b][jCD * DIM], xd, tag, l);
    __syncthreads();

    // ---- Phase D: sample-merge linear; lanes 0-15 use xd, 16-31 leaf; publish h1 ----
    {
        float x[8];
        if (l < 16) ld8s(&xd[8 * l], x);
        else        ld8s(&leaf[10 + jCD][0] + 8 * (l - 16), x);
        float a0 = 0.f, a1 = 0.f;
        #pragma unroll
        for (int m = 0; m < 8; m++) {
            a0 = fmaf(x[m], wD0r[m], a0);
            a1 = fmaf(x[m], wD1r[m], a1);
        }
        float r0 = wred(a0), r1 = wred(a1);
        if (l == 0)      st_tag(&g_h1x[b][jCD * DIM + k0], prelu_f(r0 + bD0, A1), tag);
        else if (l == 1) st_tag(&g_h1x[b][jCD * DIM + k1], prelu_f(r1 + bD1, A1), tag);
    }

    // ---- Boundary E: warp0 polls h1 (256 floats); others load Phase-F weights ----
    float wFr[8];
    {
        const float4* pF = (const float4*)(Ws0 + (long)kB * 256 + 8 * l);
        ((float4*)wFr)[0] = pF[0]; ((float4*)wFr)[1] = pF[1];
    }
    if (w == 0) poll_bcast<8>(&g_h1x[b][0], xe, tag, l);
    __syncthreads();

    // ---- Phase E: root bilinear from smem xe; publish tagged tb0 ----
    {
        float x[8];
        ld8s(&xe[8 * l], x);
        float a0 = 0.f, a1 = 0.f, a2 = 0.f;
        #pragma unroll
        for (int m = 0; m < 8; m++) {
            a0 = fmaf(x[m], wEr[3 * m + 0], a0);
            a1 = fmaf(x[m], wEr[3 * m + 1], a1);
            a2 = fmaf(x[m], wEr[3 * m + 2], a2);
        }
        float z = a0 * svec0[0] + a1 * svec0[1] + a2 * svec0[2];
        float r = wred(z);
        if (l == 0) st_tag(&g_tb0x[b][kB], prelu_f(r + bE, A0), tag);
    }

    // ---- Boundary F: warp0 polls tb0 ----
    if (w == 0) poll_bcast<4>(&g_tb0x[b][0], xf, tag, l);
    __syncthreads();

    // ---- Phase F: root linear; lanes 0-15 use xf, 16-31 xh24 ----
    {
        float x[8];
        if (l < 16) ld8s(&xf[8 * l], x);
        else        ld8s(&xh24[8 * (l - 16)], x);
        float acc = 0.f;
        #pragma unroll
        for (int m = 0; m < 8; m++) acc = fmaf(x[m], wFr[m], acc);
        float r = wred(acc);
        if (l == 0) out[(long)b * DIM + kB] = prelu_f(r + bF, A0);
    }
}

extern "C" void kernel_launch(void* const* d_in, const int* in_sizes, int n_in,
                              void* d_out, int out_size)
{
    const float* points = (const float*)d_in[0];
    const float* vec2   = (const float*)d_in[1];
    const float* vec1   = (const float*)d_in[2];
    const float* vec0   = (const float*)d_in[3];
    const float* Wp     = (const float*)d_in[4];
    const float* bp     = (const float*)d_in[5];
    const float* a_leaf = (const float*)d_in[6];
    const float* Wb2    = (const float*)d_in[7];
    const float* bb2    = (const float*)d_in[8];
    const float* a2     = (const float*)d_in[9];
    const float* Wb1    = (const float*)d_in[10];
    const float* bb1    = (const float*)d_in[11];
    const float* Ws1    = (const float*)d_in[12];
    const float* bs1    = (const float*)d_in[13];
    const float* a1     = (const float*)d_in[14];
    const float* Wb0    = (const float*)d_in[15];
    const float* bb0    = (const float*)d_in[16];
    const float* Ws0    = (const float*)d_in[17];
    const float* bs0    = (const float*)d_in[18];
    const float* a0     = (const float*)d_in[19];
    const int*   cl2    = (const int*)d_in[20];
    const int*   cr2    = (const int*)d_in[21];
    const int*   cl1    = (const int*)d_in[22];
    const int*   cr1    = (const int*)d_in[23];
    const int*   cs1    = (const int*)d_in[24];
    const int*   cl0    = (const int*)d_in[25];
    const int*   cr0    = (const int*)d_in[26];
    const int*   cs0    = (const int*)d_in[27];

    const int B  = out_size / DIM;          // 8
    const int N3 = in_sizes[0] / (3 * B);   // 131072
    const int N2 = in_sizes[1] / (3 * B);   // 65536
    const int N1 = in_sizes[2] / (3 * B);   // 1024

    encoder_fused_kernel<<<B * NSLICE, NTHREADS>>>(
        points, vec2, vec1, vec0,
        Wp, bp, a_leaf, Wb2, bb2, a2,
        Wb1, bb1, Ws1, bs1, a1,
        Wb0, bb0, Ws0, bs0, a0,
        cl2, cr2, cl1, cr1, cs1, cl0, cr0, cs0,
        (float*)d_out, N3, N2, N1);
}

// round 17
// speedup vs baseline: 1.1557x; 1.1557x over previous
#include <cuda_runtime.h>
#include <cstdint>

#define DIM 128
#define NSLICE 8           // k-slices (blocks) per batch
#define NTHREADS 256       // 8 warps per block
#define NBATCH 8

// ---------------- global scratch (static __device__, no allocation) ----------------
// Row adjacency is load-bearing: h2[2j]||h2[2j+1] and h1[0]||h1[1] read as
// 256 contiguous floats by d-contiguous lanes.
__device__ float g_h2[NBATCH][5][DIM];
__device__ float g_tb[NBATCH][2][DIM];
__device__ float g_h1[NBATCH][2][DIM];
__device__ float g_tb0[NBATCH][DIM];

// per-(batch,phase) barrier: ONE monotonic counter, own 128B line
struct __align__(128) BarSlot { unsigned c; unsigned pad[31]; };
__device__ BarSlot g_bar[NBATCH * 4];

__device__ __forceinline__ float prelu_f(float x, float a) {
    return x >= 0.0f ? x : a * x;
}

// xor-butterfly: full sum in EVERY lane
__device__ __forceinline__ float wred(float v) {
    v += __shfl_xor_sync(0xffffffffu, v, 16);
    v += __shfl_xor_sync(0xffffffffu, v, 8);
    v += __shfl_xor_sync(0xffffffffu, v, 4);
    v += __shfl_xor_sync(0xffffffffu, v, 2);
    v += __shfl_xor_sync(0xffffffffu, v, 1);
    return v;
}

__device__ __forceinline__ void bar_arrive(int slot) {
    asm volatile("red.release.gpu.global.add.u32 [%0], %1;"
                 :: "l"(&g_bar[slot].c), "r"(1u) : "memory");
}

__device__ __forceinline__ void bar_poll(int slot, unsigned target) {
    unsigned cur;
    do {
        asm volatile("ld.acquire.gpu.global.u32 %0, [%1];"
                     : "=r"(cur) : "l"(&g_bar[slot].c) : "memory");
    } while ((int)(cur - target) < 0);
}

// load 8 consecutive floats (32B-aligned) into x[8]
__device__ __forceinline__ void ld8(const float* p, float* x) {
    float4 a = ((const float4*)p)[0];
    float4 b = ((const float4*)p)[1];
    x[0]=a.x; x[1]=a.y; x[2]=a.z; x[3]=a.w;
    x[4]=b.x; x[5]=b.y; x[6]=b.z; x[7]=b.w;
}

__global__ __launch_bounds__(NTHREADS, 1) void encoder_fused_kernel(
    const float* __restrict__ points,  // [B, N3, 3]
    const float* __restrict__ vec2,    // [B, N2, 3]
    const float* __restrict__ vec1,    // [B, N1, 3]
    const float* __restrict__ vec0,    // [B, 1, 3]
    const float* __restrict__ Wp,      // [DIM, 3]
    const float* __restrict__ bp,
    const float* __restrict__ a_leaf,
    const float* __restrict__ Wb2, const float* __restrict__ bb2,
    const float* __restrict__ a2p,
    const float* __restrict__ Wb1, const float* __restrict__ bb1,
    const float* __restrict__ Ws1, const float* __restrict__ bs1,
    const float* __restrict__ a1p,
    const float* __restrict__ Wb0, const float* __restrict__ bb0,
    const float* __restrict__ Ws0, const float* __restrict__ bs0,
    const float* __restrict__ a0p,
    const int* __restrict__ cl2, const int* __restrict__ cr2,
    const int* __restrict__ cl1, const int* __restrict__ cr1,
    const int* __restrict__ cs1,
    const int* __restrict__ cl0, const int* __restrict__ cr0,
    const int* __restrict__ cs0,
    float* __restrict__ out,           // [B, DIM]
    int N3, int N2n, int N1n)
{
    const int b   = blockIdx.x >> 3;             // batch
    const int s   = blockIdx.x & (NSLICE - 1);   // k-slice
    const int tid = threadIdx.x;
    const int w   = tid >> 5, l = tid & 31;

    // ---- precompute replay-safe barrier targets (thread 0; overlaps preload) ----
    unsigned tgt0 = 0, tgt1 = 0, tgt2 = 0, tgt3 = 0;
    if (tid == 0) {
        unsigned v;
        asm volatile("ld.acquire.gpu.global.u32 %0, [%1];" : "=r"(v) : "l"(&g_bar[b*4+0].c));
        tgt0 = (v / NSLICE) * NSLICE + NSLICE;
        asm volatile("ld.acquire.gpu.global.u32 %0, [%1];" : "=r"(v) : "l"(&g_bar[b*4+1].c));
        tgt1 = (v / NSLICE) * NSLICE + NSLICE;
        asm volatile("ld.acquire.gpu.global.u32 %0, [%1];" : "=r"(v) : "l"(&g_bar[b*4+2].c));
        tgt2 = (v / NSLICE) * NSLICE + NSLICE;
        asm volatile("ld.acquire.gpu.global.u32 %0, [%1];" : "=r"(v) : "l"(&g_bar[b*4+3].c));
        tgt3 = (v / NSLICE) * NSLICE + NSLICE;
    }

    // ---------------- work mapping (NSLICE=8) ----------------
    // B/E/F: 16 channels per block, 2 per warp: c0, c1
    const int c0 = (s << 4) + (w << 1);
    const int c1 = c0 + 1;
    // C/D: 32 outputs per block, 4 per warp; j fixed per block (idx span 32)
    const int idx = (s << 5) + (w << 2);
    const int jCD = idx >> 7;
    const int kd  = idx & 127;              // kd..kd+3

    // ---- preload ONLY Phase-B weights up front; rest deferred into barrier waits ----
    float wB0r[24], wB1r[24];
    {
        const float4* p0 = (const float4*)(Wb2 + (long)c0 * 768 + 24 * l);
        const float4* p1 = (const float4*)(Wb2 + (long)c1 * 768 + 24 * l);
        #pragma unroll
        for (int i = 0; i < 6; i++) {
            ((float4*)wB0r)[i] = p0[i];
            ((float4*)wB1r)[i] = p1[i];
        }
    }
    const float bB0 = bb2[c0], bB1 = bb2[c1];
    float bC[4], bD[4];
    #pragma unroll
    for (int i = 0; i < 4; i++) { bC[i] = bb1[kd + i]; bD[i] = bs1[kd + i]; }
    const float bE0 = bb0[c0], bE1 = bb0[c1];
    const float bF0 = bs0[c0], bF1 = bs0[c1];
    const float AL = a_leaf[0], A2 = a2p[0], A1 = a1p[0], A0 = a0p[0];

    __shared__ int sroot[3];
    __shared__ int scl1[1024], scr1[1024], scs1[1024];   // level-1 tables (12KB)
    __shared__ int sp[12];
    __shared__ __align__(16) float svec2[5][3];
    __shared__ __align__(16) float svec1[2][3];
    __shared__ __align__(16) float svec0[3];
    __shared__ __align__(16) float leaf[12][DIM];

    const bool bulk = (N1n == 1024);

    // ---- Round 1: root indices (thread 0) PARALLEL WITH level-1 table bulk load ----
    if (tid == 0) {
        sroot[0] = cl0[0]; sroot[1] = cr0[0]; sroot[2] = cs0[0];
    }
    if (bulk) {
        #pragma unroll
        for (int i = 0; i < 4; i++) {
            int j = tid + i * NTHREADS;
            scl1[j] = cl1[j];
            scr1[j] = cr1[j];
            scs1[j] = cs1[j];
        }
    }
    __syncthreads();

    const int l1a = sroot[0], l1b = sroot[1], n4 = sroot[2];
    int n0, n1, n2_, n3;
    if (bulk) {
        n0 = scl1[l1a]; n1 = scr1[l1a]; n2_ = scl1[l1b]; n3 = scr1[l1b];
    } else {
        n0 = cl1[l1a];  n1 = cr1[l1a];  n2_ = cl1[l1b];  n3 = cr1[l1b];
    }

    // ---- Round 2: distributed cl2/cr2 gather + sample leaves + ALL vec gathers ----
    if (tid < 10) {
        int j = tid >> 1;
        int node = (j == 0) ? n0 : (j == 1) ? n1 : (j == 2) ? n2_ : (j == 3) ? n3 : n4;
        sp[tid] = (tid & 1) ? cr2[node] : cl2[node];
    } else if (tid == 10) {
        sp[10] = bulk ? scs1[l1a] : cs1[l1a];
    } else if (tid == 11) {
        sp[11] = bulk ? scs1[l1b] : cs1[l1b];
    } else if (tid >= 32 && tid < 47) {
        int t = tid - 32;
        int j = t / 3, v = t - 3 * j;
        int node = (j == 0) ? n0 : (j == 1) ? n1 : (j == 2) ? n2_ : (j == 3) ? n3 : n4;
        svec2[j][v] = vec2[((long)b * N2n + node) * 3 + v];
    } else if (tid >= 47 && tid < 53) {
        int t = tid - 47;
        int j = t / 3, v = t - 3 * j;
        svec1[j][v] = vec1[((long)b * N1n + (j == 0 ? l1a : l1b)) * 3 + v];
    } else if (tid >= 53 && tid < 56) {
        svec0[tid - 53] = vec0[(long)b * 3 + (tid - 53)];
    }
    __syncthreads();

    // ---- Round 3: leaves: 12 rows, h3 = prelu(points @ Wp^T + bp) ----
    for (int i = tid; i < 12 * DIM; i += NTHREADS) {
        int j = i >> 7, k = i & 127;
        const float* pt = points + ((long)b * N3 + sp[j]) * 3;
        float h = fmaf(Wp[k * 3 + 0], pt[0],
                  fmaf(Wp[k * 3 + 1], pt[1],
                  fmaf(Wp[k * 3 + 2], pt[2], bp[k])));
        leaf[j][k] = prelu_f(h, AL);
    }
    __syncthreads();

    // ---- Phase B: layer-2 bilinear, 5 nodes x 2 channels per warp ----
    {
        #pragma unroll
        for (int j = 0; j < 5; j++) {
            float x[8];
            ld8(&leaf[2 * j][0] + 8 * l, x);
            float a00=0.f,a01=0.f,a02=0.f, a10=0.f,a11=0.f,a12=0.f;
            #pragma unroll
            for (int m = 0; m < 8; m++) {
                a00 = fmaf(x[m], wB0r[3*m+0], a00);
                a01 = fmaf(x[m], wB0r[3*m+1], a01);
                a02 = fmaf(x[m], wB0r[3*m+2], a02);
                a10 = fmaf(x[m], wB1r[3*m+0], a10);
                a11 = fmaf(x[m], wB1r[3*m+1], a11);
                a12 = fmaf(x[m], wB1r[3*m+2], a12);
            }
            float z0 = a00*svec2[j][0] + a01*svec2[j][1] + a02*svec2[j][2];
            float z1 = a10*svec2[j][0] + a11*svec2[j][1] + a12*svec2[j][2];
            float r0 = wred(z0), r1 = wred(z1);
            if (l == 0)      g_h2[b][j][c0] = prelu_f(r0 + bB0, A2);
            else if (l == 1) g_h2[b][j][c1] = prelu_f(r1 + bB1, A2);
        }
    }

    // ---- Barrier 0 (inline): arrive, then load Phase-C weights DURING the wait ----
    float wCr[4][24];
    __syncthreads();
    if (tid == 0) bar_arrive(b * 4 + 0);
    {
        #pragma unroll
        for (int i = 0; i < 4; i++) {
            const float4* pC = (const float4*)(Wb1 + (long)(kd + i) * 768 + 24 * l);
            #pragma unroll
            for (int q = 0; q < 6; q++) ((float4*)wCr[i])[q] = pC[q];
        }
    }
    if (tid == 0) bar_poll(b * 4 + 0, tgt0);
    __syncthreads();

    // ---- Phase C: layer-1 bilinear, 4 channels per warp; x from global (L2-hot) ----
    {
        float x[8];
        ld8(&g_h2[b][2 * jCD][0] + 8 * l, x);
        float acc[4][3];
        #pragma unroll
        for (int i = 0; i < 4; i++) { acc[i][0]=0.f; acc[i][1]=0.f; acc[i][2]=0.f; }
        #pragma unroll
        for (int m = 0; m < 8; m++) {
            #pragma unroll
            for (int i = 0; i < 4; i++) {
                acc[i][0] = fmaf(x[m], wCr[i][3*m+0], acc[i][0]);
                acc[i][1] = fmaf(x[m], wCr[i][3*m+1], acc[i][1]);
                acc[i][2] = fmaf(x[m], wCr[i][3*m+2], acc[i][2]);
            }
        }
        #pragma unroll
        for (int i = 0; i < 4; i++) {
            float z = acc[i][0]*svec1[jCD][0] + acc[i][1]*svec1[jCD][1]
                    + acc[i][2]*svec1[jCD][2];
            float r = wred(z);
            if (l == i) g_tb[b][jCD][kd + i] = prelu_f(r + bC[i], A1);
        }
    }

    // ---- Barrier 1 (inline): arrive, then load Phase-D + Phase-E weights ----
    float wDr[4][8], wE0r[24], wE1r[24];
    __syncthreads();
    if (tid == 0) bar_arrive(b * 4 + 1);
    {
        #pragma unroll
        for (int i = 0; i < 4; i++) {
            const float4* pD = (const float4*)(Ws1 + (long)(kd + i) * 256 + 8 * l);
            ((float4*)wDr[i])[0] = pD[0]; ((float4*)wDr[i])[1] = pD[1];
        }
        const float4* pE0 = (const float4*)(Wb0 + (long)c0 * 768 + 24 * l);
        const float4* pE1 = (const float4*)(Wb0 + (long)c1 * 768 + 24 * l);
        #pragma unroll
        for (int q = 0; q < 6; q++) {
            ((float4*)wE0r)[q] = pE0[q];
            ((float4*)wE1r)[q] = pE1[q];
        }
    }
    if (tid == 0) bar_poll(b * 4 + 1, tgt1);
    __syncthreads();

    // ---- Phase D: sample-merge linear, 4 channels; lanes 0-15 tb, 16-31 leaf ----
    {
        float x[8];
        if (l < 16) ld8(&g_tb[b][jCD][0] + 8 * l, x);
        else        ld8(&leaf[10 + jCD][0] + 8 * (l - 16), x);
        float acc[4] = {0.f, 0.f, 0.f, 0.f};
        #pragma unroll
        for (int m = 0; m < 8; m++) {
            #pragma unroll
            for (int i = 0; i < 4; i++)
                acc[i] = fmaf(x[m], wDr[i][m], acc[i]);
        }
        #pragma unroll
        for (int i = 0; i < 4; i++) {
            float r = wred(acc[i]);
            if (l == i) g_h1[b][jCD][kd + i] = prelu_f(r + bD[i], A1);
        }
    }

    // ---- Barrier 2 (inline): arrive, then load Phase-F weights ----
    float wF0r[8], wF1r[8];
    __syncthreads();
    if (tid == 0) bar_arrive(b * 4 + 2);
    {
        const float4* pF0 = (const float4*)(Ws0 + (long)c0 * 256 + 8 * l);
        const float4* pF1 = (const float4*)(Ws0 + (long)c1 * 256 + 8 * l);
        ((float4*)wF0r)[0] = pF0[0]; ((float4*)wF0r)[1] = pF0[1];
        ((float4*)wF1r)[0] = pF1[0]; ((float4*)wF1r)[1] = pF1[1];
    }
    if (tid == 0) bar_poll(b * 4 + 2, tgt2);
    __syncthreads();

    // ---- Phase E: root bilinear, 2 channels; x = h1 cat (contiguous global) ----
    {
        float x[8];
        ld8(&g_h1[b][0][0] + 8 * l, x);
        float a00=0.f,a01=0.f,a02=0.f, a10=0.f,a11=0.f,a12=0.f;
        #pragma unroll
        for (int m = 0; m < 8; m++) {
            a00 = fmaf(x[m], wE0r[3*m+0], a00);
            a01 = fmaf(x[m], wE0r[3*m+1], a01);
            a02 = fmaf(x[m], wE0r[3*m+2], a02);
            a10 = fmaf(x[m], wE1r[3*m+0], a10);
            a11 = fmaf(x[m], wE1r[3*m+1], a11);
            a12 = fmaf(x[m], wE1r[3*m+2], a12);
        }
        float z0 = a00*svec0[0] + a01*svec0[1] + a02*svec0[2];
        float z1 = a10*svec0[0] + a11*svec0[1] + a12*svec0[2];
        float r0 = wred(z0), r1 = wred(z1);
        if (l == 0)      g_tb0[b][c0] = prelu_f(r0 + bE0, A0);
        else if (l == 1) g_tb0[b][c1] = prelu_f(r1 + bE1, A0);
    }

    // ---- Barrier 3 ----
    __syncthreads();
    if (tid == 0) { bar_arrive(b * 4 + 3); bar_poll(b * 4 + 3, tgt3); }
    __syncthreads();

    // ---- Phase F: root linear, 2 channels; lanes 0-15 tb0, 16-31 h2[4] ----
    {
        float x[8];
        if (l < 16) ld8(&g_tb0[b][0] + 8 * l, x);
        else        ld8(&g_h2[b][4][0] + 8 * (l - 16), x);
        float a0 = 0.f, a1 = 0.f;
        #pragma unroll
        for (int m = 0; m < 8; m++) {
            a0 = fmaf(x[m], wF0r[m], a0);
            a1 = fmaf(x[m], wF1r[m], a1);
        }
        float r0 = wred(a0), r1 = wred(a1);
        if (l == 0)      out[(long)b * DIM + c0] = prelu_f(r0 + bF0, A0);
        else if (l == 1) out[(long)b * DIM + c1] = prelu_f(r1 + bF1, A0);
    }
}

extern "C" void kernel_launch(void* const* d_in, const int* in_sizes, int n_in,
                              void* d_out, int out_size)
{
    const float* points = (const float*)d_in[0];
    const float* vec2   = (const float*)d_in[1];
    const float* vec1   = (const float*)d_in[2];
    const float* vec0   = (const float*)d_in[3];
    const float* Wp     = (const float*)d_in[4];
    const float* bp     = (const float*)d_in[5];
    const float* a_leaf = (const float*)d_in[6];
    const float* Wb2    = (const float*)d_in[7];
    const float* bb2    = (const float*)d_in[8];
    const float* a2     = (const float*)d_in[9];
    const float* Wb1    = (const float*)d_in[10];
    const float* bb1    = (const float*)d_in[11];
    const float* Ws1    = (const float*)d_in[12];
    const float* bs1    = (const float*)d_in[13];
    const float* a1     = (const float*)d_in[14];
    const float* Wb0    = (const float*)d_in[15];
    const float* bb0    = (const float*)d_in[16];
    const float* Ws0    = (const float*)d_in[17];
    const float* bs0    = (const float*)d_in[18];
    const float* a0     = (const float*)d_in[19];
    const int*   cl2    = (const int*)d_in[20];
    const int*   cr2    = (const int*)d_in[21];
    const int*   cl1    = (const int*)d_in[22];
    const int*   cr1    = (const int*)d_in[23];
    const int*   cs1    = (const int*)d_in[24];
    const int*   cl0    = (const int*)d_in[25];
    const int*   cr0    = (const int*)d_in[26];
    const int*   cs0    = (const int*)d_in[27];

    const int B  = out_size / DIM;          // 8
    const int N3 = in_sizes[0] / (3 * B);   // 131072
    const int N2 = in_sizes[1] / (3 * B);   // 65536
    const int N1 = in_sizes[2] / (3 * B);   // 1024

    encoder_fused_kernel<<<B * NSLICE, NTHREADS>>>(
        points, vec2, vec1, vec0,
        Wp, bp, a_leaf, Wb2, bb2, a2,
        Wb1, bb1, Ws1, bs1, a1,
        Wb0, bb0, Ws0, bs0, a0,
        cl2, cr2, cl1, cr1, cs1, cl0, cr0, cs0,
        (float*)d_out, N3, N2, N1);
}